// round 10
// baseline (speedup 1.0000x reference)
#include <cuda_runtime.h>
#include <cuda_bf16.h>

// GaussianKernelLoss: B=32, N=16, H=W=256, SIGMA=0.1, RADIUS=0.2
// d_in[0]=pred [32,16,2] f32, d_in[1]=target [32,16,2] f32,
// d_in[2]=visibility [32,16] f32, d_in[3]=coord_grid [2,256,256] f32 (linspace i/255)
// Output: scalar f32.

#define BN     512
#define RADIUS 0.2f
#define R2     (0.2f * 0.2f)
#define COEF   (-50.0f)        // -1/(2*sigma^2)
#define INV255 (1.0f / 255.0f)
#define NCOL   4               // 4*32 = 128 >= max bbox width (<=104 exact)
#define NTHR   256             // 8 warps per block, 1 landmark per block
#define NGRP   32              // arrival groups
#define GSIZE  16              // blocks per group (NGRP*GSIZE == BN)

__device__ float gN[BN];            // per-landmark numerator partials
__device__ float gD[BN];            // per-landmark denominator partials
// Spread counters 32 ints (128B) apart so each lands in its own L2 sector
// and the per-address atomic serialization chains stay short (~16 deep).
__device__ int   g_grp[NGRP * 32];  // zero-init; self-reset each launch
__device__ int   g_master;          // zero-init; reset by final block

__global__ __launch_bounds__(NTHR)
void gkl_fused_kernel(const float* __restrict__ pred,
                      const float* __restrict__ tgt,
                      const float* __restrict__ vis,
                      const float* __restrict__ grid,
                      float* __restrict__ out)
{
    const int lm  = blockIdx.x;
    const int tid = threadIdx.x;
    const int cx  = tid & 31;   // lane -> column subset
    const int cy  = tid >> 5;   // warp (0..7) -> row residue (stride 8)

    __shared__ float redN[8], redD[8];
    __shared__ int   sIsLast;

    float num0 = 0.0f, den0 = 0.0f;     // two independent accumulator chains
    float num1 = 0.0f, den1 = 0.0f;
    const float v = vis[lm];

    if (v >= 0.5f) {
        const float2 t2v = ((const float2*)tgt)[lm];
        const float2 p2v = ((const float2*)pred)[lm];
        const float tx = t2v.x, ty = t2v.y;
        const float px = p2v.x, py = p2v.y;

        // Exact bounding box of the radius disk (per-pixel mask is exact).
        const int x0 = max(0,   (int)floorf((tx - RADIUS) * 255.0f));
        const int y0 = max(0,   (int)floorf((ty - RADIUS) * 255.0f));
        const int x1 = min(255, (int)ceilf ((tx + RADIUS) * 255.0f));
        const int y1 = min(255, (int)ceilf ((ty + RADIUS) * 255.0f));
        const int bw = x1 - x0 + 1;
        const int bh = y1 - y0 + 1;

        // Column tables in registers: lane cx owns columns cx + 32k.
        // Out-of-range columns poisoned (Ex=0, T2=huge) -> contribute 0.
        float cT2[NCOL], cP2[NCOL], cEx[NCOL];
        #pragma unroll
        for (int k = 0; k < NCOL; k++) {
            const int j   = cx + 32 * k;
            const bool ok = (j < bw);
            const float xv = (float)(x0 + j) * INV255;   // coord_grid == linspace
            const float dt = xv - tx;
            const float dp = xv - px;
            cT2[k] = ok ? dt * dt : 1e9f;
            cP2[k] = dp * dp;
            cEx[k] = ok ? __expf(COEF * dt * dt) : 0.0f;
        }

        // Incremental row coordinates: chain A = rows cy+16n, chain B = rows
        // cy+8+16n; both advanced by 16*INV255 per iteration (stride-8 overall).
        const float base = (float)y0 * INV255;
        float dtyA = fmaf((float)cy,       INV255, base - ty);
        float dpyA = fmaf((float)cy,       INV255, base - py);
        float dtyB = fmaf((float)(cy + 8), INV255, base - ty);
        float dpyB = fmaf((float)(cy + 8), INV255, base - py);
        const float STEP = 16.0f * INV255;

        int i = cy;
        for (; i + 8 < bh; i += 16) {
            {   // row i (chain A)
                const float t2y = dtyA * dtyA;
                const float p2y = dpyA * dpyA;
                const float ey  = __expf(COEF * t2y);
                const float lim = R2 - t2y;
                #pragma unroll
                for (int k = 0; k < NCOL; k++) {
                    const float d2p = cP2[k] + p2y;
                    const float w   = cEx[k] * ey;
                    float d;
                    asm("sqrt.approx.f32 %0, %1;" : "=f"(d) : "f"(d2p));
                    if (cT2[k] <= lim) {
                        num0 = fmaf(w, d, num0);
                        den0 += w;
                    }
                }
                dtyA += STEP; dpyA += STEP;
            }
            {   // row i+8 (chain B)
                const float t2y = dtyB * dtyB;
                const float p2y = dpyB * dpyB;
                const float ey  = __expf(COEF * t2y);
                const float lim = R2 - t2y;
                #pragma unroll
                for (int k = 0; k < NCOL; k++) {
                    const float d2p = cP2[k] + p2y;
                    const float w   = cEx[k] * ey;
                    float d;
                    asm("sqrt.approx.f32 %0, %1;" : "=f"(d) : "f"(d2p));
                    if (cT2[k] <= lim) {
                        num1 = fmaf(w, d, num1);
                        den1 += w;
                    }
                }
                dtyB += STEP; dpyB += STEP;
            }
        }
        if (i < bh) {   // remainder row (chain A)
            const float t2y = dtyA * dtyA;
            const float p2y = dpyA * dpyA;
            const float ey  = __expf(COEF * t2y);
            const float lim = R2 - t2y;
            #pragma unroll
            for (int k = 0; k < NCOL; k++) {
                const float d2p = cP2[k] + p2y;
                const float w   = cEx[k] * ey;
                float d;
                asm("sqrt.approx.f32 %0, %1;" : "=f"(d) : "f"(d2p));
                if (cT2[k] <= lim) {
                    num0 = fmaf(w, d, num0);
                    den0 += w;
                }
            }
        }
    }

    float num = num0 + num1;
    float den = den0 + den1;

    // Block reduction (8 warps) — uniform path for all blocks.
    #pragma unroll
    for (int o = 16; o; o >>= 1) {
        num += __shfl_xor_sync(0xffffffffu, num, o);
        den += __shfl_xor_sync(0xffffffffu, den, o);
    }
    if (cx == 0) { redN[cy] = num; redD[cy] = den; }
    __syncthreads();

    // Hierarchical arrival: block -> group counter (16-deep chain) ->
    // master counter (32-deep chain). Replaces the 512-deep single-address
    // atomic serialization that was the kernel's critical path.
    if (tid == 0) {
        float n = 0.0f, d = 0.0f;
        #pragma unroll
        for (int k = 0; k < 8; k++) { n += redN[k]; d += redD[k]; }
        gN[lm] = n;
        gD[lm] = d;
        __threadfence();
        const int grp = lm >> 4;                       // 32 groups of 16
        int last = 0;
        if (atomicAdd(&g_grp[grp * 32], 1) == GSIZE - 1) {
            g_grp[grp * 32] = 0;                       // all 16 arrived; safe reset
            if (atomicAdd(&g_master, 1) == NGRP - 1) last = 1;
        }
        sIsLast = last;
    }
    __syncthreads();

    // Final block divides per landmark and folds to the scalar output.
    if (sIsLast) {
        __threadfence();
        float s = 0.0f;
        #pragma unroll
        for (int h = 0; h < 2; h++) {           // landmarks tid, tid+256
            const int l = tid + 256 * h;
            const float n = __ldcg(&gN[l]);
            const float d = __ldcg(&gD[l]);
            s += n / (d + 1e-8f);               // invisible: 0/1e-8 = 0
        }
        #pragma unroll
        for (int o = 16; o; o >>= 1) s += __shfl_xor_sync(0xffffffffu, s, o);
        if (cx == 0) redN[cy] = s;
        __syncthreads();
        if (tid == 0) {
            float t = 0.0f;
            #pragma unroll
            for (int k = 0; k < 8; k++) t += redN[k];
            *out = t / (512.0f + 1e-8f);
            g_master = 0;                       // reset for next graph replay
        }
    }
}

extern "C" void kernel_launch(void* const* d_in, const int* in_sizes, int n_in,
                              void* d_out, int out_size)
{
    const float* pred = (const float*)d_in[0];
    const float* tgt  = (const float*)d_in[1];
    const float* vis  = (const float*)d_in[2];
    const float* grid = (const float*)d_in[3];
    gkl_fused_kernel<<<BN, NTHR>>>(pred, tgt, vis, grid, (float*)d_out);
}

// round 11
// speedup vs baseline: 1.0362x; 1.0362x over previous
#include <cuda_runtime.h>
#include <cuda_bf16.h>

// GaussianKernelLoss: B=32, N=16, H=W=256, SIGMA=0.1, RADIUS=0.2
// d_in[0]=pred [32,16,2] f32, d_in[1]=target [32,16,2] f32,
// d_in[2]=visibility [32,16] f32, d_in[3]=coord_grid [2,256,256] f32 (linspace i/255)
// Output: scalar f32.

#define BN     512
#define RADIUS 0.2f
#define R2     (0.2f * 0.2f)
#define COEF   (-50.0f)        // -1/(2*sigma^2)
#define INV255 (1.0f / 255.0f)
#define NCOL   4               // 4*32 = 128 >= max bbox width (<=104 exact)
#define NTHR   256             // 8 warps per block, 1 landmark per block

__device__ float gN[BN];       // per-landmark numerator partials
__device__ float gD[BN];       // per-landmark denominator partials
__device__ int   g_count;      // zero-init; last block resets each launch

// sqrt(x) on FMA/ALU pipes only (no MUFU): magic-constant rsqrt seed +
// two Newton iterations, then d = x * rsqrt(x). Rel err ~1e-5.
__device__ __forceinline__ float fma_sqrt(float x)
{
    x = fmaxf(x, 1e-20f);                       // guard x==0 -> NaN
    float y = __uint_as_float(0x5f3759dfu - (__float_as_uint(x) >> 1));
    const float xh = 0.5f * x;
    y = y * fmaf(-xh * y, y, 1.5f);             // Newton 1
    y = y * fmaf(-xh * y, y, 1.5f);             // Newton 2
    return x * y;
}

__global__ __launch_bounds__(NTHR)
void gkl_fused_kernel(const float* __restrict__ pred,
                      const float* __restrict__ tgt,
                      const float* __restrict__ vis,
                      const float* __restrict__ grid,
                      float* __restrict__ out)
{
    const int lm  = blockIdx.x;
    const int tid = threadIdx.x;
    const int cx  = tid & 31;   // lane -> column subset
    const int cy  = tid >> 5;   // warp (0..7) -> row residue (stride 8)

    __shared__ float redN[8], redD[8];
    __shared__ int   sIsLast;

    float num0 = 0.0f, den0 = 0.0f;     // two independent accumulator chains
    float num1 = 0.0f, den1 = 0.0f;
    const float v = vis[lm];

    if (v >= 0.5f) {
        const float2 t2v = ((const float2*)tgt)[lm];
        const float2 p2v = ((const float2*)pred)[lm];
        const float tx = t2v.x, ty = t2v.y;
        const float px = p2v.x, py = p2v.y;

        // Exact bounding box of the radius disk (per-pixel mask is exact).
        const int x0 = max(0,   (int)floorf((tx - RADIUS) * 255.0f));
        const int y0 = max(0,   (int)floorf((ty - RADIUS) * 255.0f));
        const int x1 = min(255, (int)ceilf ((tx + RADIUS) * 255.0f));
        const int y1 = min(255, (int)ceilf ((ty + RADIUS) * 255.0f));
        const int bw = x1 - x0 + 1;
        const int bh = y1 - y0 + 1;

        // Column tables in registers: lane cx owns columns cx + 32k.
        // Out-of-range columns poisoned (Ex=0, T2=huge) -> contribute 0.
        float cT2[NCOL], cP2[NCOL], cEx[NCOL];
        #pragma unroll
        for (int k = 0; k < NCOL; k++) {
            const int j   = cx + 32 * k;
            const bool ok = (j < bw);
            const float xv = (float)(x0 + j) * INV255;   // coord_grid == linspace
            const float dt = xv - tx;
            const float dp = xv - px;
            cT2[k] = ok ? dt * dt : 1e9f;
            cP2[k] = dp * dp;
            cEx[k] = ok ? __expf(COEF * dt * dt) : 0.0f;
        }

        // Incremental row coordinates: chain A = rows cy+16n, chain B = rows
        // cy+8+16n; both advanced by 16*INV255 per iteration (stride-8 overall).
        const float base = (float)y0 * INV255;
        float dtyA = fmaf((float)cy,       INV255, base - ty);
        float dpyA = fmaf((float)cy,       INV255, base - py);
        float dtyB = fmaf((float)(cy + 8), INV255, base - ty);
        float dpyB = fmaf((float)(cy + 8), INV255, base - py);
        const float STEP = 16.0f * INV255;

        int i = cy;
        for (; i + 8 < bh; i += 16) {
            {   // row i (chain A)
                const float t2y = dtyA * dtyA;
                const float p2y = dpyA * dpyA;
                const float ey  = __expf(COEF * t2y);
                const float lim = R2 - t2y;
                #pragma unroll
                for (int k = 0; k < NCOL; k++) {
                    const float d2p = cP2[k] + p2y;
                    const float w   = cEx[k] * ey;
                    const float d   = fma_sqrt(d2p);
                    if (cT2[k] <= lim) {
                        num0 = fmaf(w, d, num0);
                        den0 += w;
                    }
                }
                dtyA += STEP; dpyA += STEP;
            }
            {   // row i+8 (chain B)
                const float t2y = dtyB * dtyB;
                const float p2y = dpyB * dpyB;
                const float ey  = __expf(COEF * t2y);
                const float lim = R2 - t2y;
                #pragma unroll
                for (int k = 0; k < NCOL; k++) {
                    const float d2p = cP2[k] + p2y;
                    const float w   = cEx[k] * ey;
                    const float d   = fma_sqrt(d2p);
                    if (cT2[k] <= lim) {
                        num1 = fmaf(w, d, num1);
                        den1 += w;
                    }
                }
                dtyB += STEP; dpyB += STEP;
            }
        }
        if (i < bh) {   // remainder row (chain A)
            const float t2y = dtyA * dtyA;
            const float p2y = dpyA * dpyA;
            const float ey  = __expf(COEF * t2y);
            const float lim = R2 - t2y;
            #pragma unroll
            for (int k = 0; k < NCOL; k++) {
                const float d2p = cP2[k] + p2y;
                const float w   = cEx[k] * ey;
                const float d   = fma_sqrt(d2p);
                if (cT2[k] <= lim) {
                    num0 = fmaf(w, d, num0);
                    den0 += w;
                }
            }
        }
    }

    float num = num0 + num1;
    float den = den0 + den1;

    // Block reduction (8 warps) — uniform path for all blocks.
    #pragma unroll
    for (int o = 16; o; o >>= 1) {
        num += __shfl_xor_sync(0xffffffffu, num, o);
        den += __shfl_xor_sync(0xffffffffu, den, o);
    }
    if (cx == 0) { redN[cy] = num; redD[cy] = den; }
    __syncthreads();

    if (tid == 0) {
        float n = 0.0f, d = 0.0f;
        #pragma unroll
        for (int k = 0; k < 8; k++) { n += redN[k]; d += redD[k]; }
        gN[lm] = n;
        gD[lm] = d;
        __threadfence();
        const int c = atomicAdd(&g_count, 1);
        sIsLast = (c == BN - 1);
    }
    __syncthreads();

    // Last block divides per landmark and folds to the scalar output.
    if (sIsLast) {
        float s = 0.0f;
        #pragma unroll
        for (int h = 0; h < 2; h++) {           // landmarks tid, tid+256
            const int l = tid + 256 * h;
            const float n = __ldcg(&gN[l]);
            const float d = __ldcg(&gD[l]);
            s += n / (d + 1e-8f);               // invisible: 0/1e-8 = 0
        }
        #pragma unroll
        for (int o = 16; o; o >>= 1) s += __shfl_xor_sync(0xffffffffu, s, o);
        if (cx == 0) redN[cy] = s;
        __syncthreads();
        if (tid == 0) {
            float t = 0.0f;
            #pragma unroll
            for (int k = 0; k < 8; k++) t += redN[k];
            *out = t / (512.0f + 1e-8f);
            g_count = 0;                        // reset for next graph replay
        }
    }
}

extern "C" void kernel_launch(void* const* d_in, const int* in_sizes, int n_in,
                              void* d_out, int out_size)
{
    const float* pred = (const float*)d_in[0];
    const float* tgt  = (const float*)d_in[1];
    const float* vis  = (const float*)d_in[2];
    const float* grid = (const float*)d_in[3];
    gkl_fused_kernel<<<BN, NTHR>>>(pred, tgt, vis, grid, (float*)d_out);
}

// round 12
// speedup vs baseline: 1.0553x; 1.0184x over previous
#include <cuda_runtime.h>
#include <cuda_bf16.h>

// GaussianKernelLoss: B=32, N=16, H=W=256, SIGMA=0.1, RADIUS=0.2
// d_in[0]=pred [32,16,2] f32, d_in[1]=target [32,16,2] f32,
// d_in[2]=visibility [32,16] f32, d_in[3]=coord_grid [2,256,256] f32 (linspace i/255)
// Output: scalar f32.

#define BN     512
#define RADIUS 0.2f
#define R2     (0.2f * 0.2f)
#define COEF   (-50.0f)        // -1/(2*sigma^2)
#define INV255 (1.0f / 255.0f)
#define NCOL   4               // 4*32 = 128 >= max bbox width (<=104 exact)
#define NTHR   256             // 8 warps per block, 1 landmark per block

__device__ float g_sum;        // zero-init; accumulated quotients; reset each launch
__device__ int   g_count;      // zero-init; completion counter; reset each launch

__global__ __launch_bounds__(NTHR)
void gkl_fused_kernel(const float* __restrict__ pred,
                      const float* __restrict__ tgt,
                      const float* __restrict__ vis,
                      const float* __restrict__ grid,
                      float* __restrict__ out)
{
    const int lm  = blockIdx.x;
    const int tid = threadIdx.x;
    const int cx  = tid & 31;   // lane -> column subset
    const int cy  = tid >> 5;   // warp (0..7) -> row residue (stride 8)

    __shared__ float redN[8], redD[8];

    // Issue all three input loads back-to-back so their latencies overlap
    // (no dependent branch between them).
    const float  v   = vis[lm];
    const float2 t2v = ((const float2*)tgt)[lm];
    const float2 p2v = ((const float2*)pred)[lm];

    float q = 0.0f;             // this block's per-landmark quotient

    if (v >= 0.5f) {
        const float tx = t2v.x, ty = t2v.y;
        const float px = p2v.x, py = p2v.y;

        // Exact bounding box of the radius disk (per-pixel mask is exact).
        const int x0 = max(0,   (int)floorf((tx - RADIUS) * 255.0f));
        const int y0 = max(0,   (int)floorf((ty - RADIUS) * 255.0f));
        const int x1 = min(255, (int)ceilf ((tx + RADIUS) * 255.0f));
        const int y1 = min(255, (int)ceilf ((ty + RADIUS) * 255.0f));
        const int bw = x1 - x0 + 1;
        const int bh = y1 - y0 + 1;

        // Column tables in registers: lane cx owns columns cx + 32k.
        // Out-of-range columns poisoned (Ex=0, T2=huge) -> contribute 0.
        float cT2[NCOL], cP2[NCOL], cEx[NCOL];
        #pragma unroll
        for (int k = 0; k < NCOL; k++) {
            const int j   = cx + 32 * k;
            const bool ok = (j < bw);
            const float xv = (float)(x0 + j) * INV255;   // coord_grid == linspace
            const float dt = xv - tx;
            const float dp = xv - px;
            cT2[k] = ok ? dt * dt : 1e9f;
            cP2[k] = dp * dp;
            cEx[k] = ok ? __expf(COEF * dt * dt) : 0.0f;
        }

        // Incremental row coordinates: chain A = rows cy+16n, chain B = rows
        // cy+8+16n; both advanced by 16*INV255 per iteration (stride-8 overall).
        const float base = (float)y0 * INV255;
        float dtyA = fmaf((float)cy,       INV255, base - ty);
        float dpyA = fmaf((float)cy,       INV255, base - py);
        float dtyB = fmaf((float)(cy + 8), INV255, base - ty);
        float dpyB = fmaf((float)(cy + 8), INV255, base - py);
        const float STEP = 16.0f * INV255;

        float num0 = 0.0f, den0 = 0.0f;
        float num1 = 0.0f, den1 = 0.0f;

        int i = cy;
        for (; i + 8 < bh; i += 16) {
            {   // row i (chain A)
                const float t2y = dtyA * dtyA;
                const float p2y = dpyA * dpyA;
                const float ey  = __expf(COEF * t2y);
                const float lim = R2 - t2y;
                #pragma unroll
                for (int k = 0; k < NCOL; k++) {
                    const float d2p = cP2[k] + p2y;
                    const float w   = cEx[k] * ey;
                    float d;
                    asm("sqrt.approx.f32 %0, %1;" : "=f"(d) : "f"(d2p));
                    if (cT2[k] <= lim) {
                        num0 = fmaf(w, d, num0);
                        den0 += w;
                    }
                }
                dtyA += STEP; dpyA += STEP;
            }
            {   // row i+8 (chain B)
                const float t2y = dtyB * dtyB;
                const float p2y = dpyB * dpyB;
                const float ey  = __expf(COEF * t2y);
                const float lim = R2 - t2y;
                #pragma unroll
                for (int k = 0; k < NCOL; k++) {
                    const float d2p = cP2[k] + p2y;
                    const float w   = cEx[k] * ey;
                    float d;
                    asm("sqrt.approx.f32 %0, %1;" : "=f"(d) : "f"(d2p));
                    if (cT2[k] <= lim) {
                        num1 = fmaf(w, d, num1);
                        den1 += w;
                    }
                }
                dtyB += STEP; dpyB += STEP;
            }
        }
        if (i < bh) {   // remainder row (chain A)
            const float t2y = dtyA * dtyA;
            const float p2y = dpyA * dpyA;
            const float ey  = __expf(COEF * t2y);
            const float lim = R2 - t2y;
            #pragma unroll
            for (int k = 0; k < NCOL; k++) {
                const float d2p = cP2[k] + p2y;
                const float w   = cEx[k] * ey;
                float d;
                asm("sqrt.approx.f32 %0, %1;" : "=f"(d) : "f"(d2p));
                if (cT2[k] <= lim) {
                    num0 = fmaf(w, d, num0);
                    den0 += w;
                }
            }
        }

        // Block reduction (uniform within this visible block).
        float num = num0 + num1;
        float den = den0 + den1;
        #pragma unroll
        for (int o = 16; o; o >>= 1) {
            num += __shfl_xor_sync(0xffffffffu, num, o);
            den += __shfl_xor_sync(0xffffffffu, den, o);
        }
        if (cx == 0) { redN[cy] = num; redD[cy] = den; }
        __syncthreads();
        if (tid == 0) {
            float n = 0.0f, d = 0.0f;
            #pragma unroll
            for (int k = 0; k < 8; k++) { n += redN[k]; d += redD[k]; }
            q = n / (d + 1e-8f);
        }
    }

    // Single-phase tail: accumulate the quotient directly; the last-arriving
    // block normalizes and writes the scalar. Adding 0 is an exact no-op, so
    // invisible blocks (and q==0) skip the value atomic entirely.
    if (tid == 0) {
        if (q != 0.0f) atomicAdd(&g_sum, q);
        __threadfence();
        if (atomicAdd(&g_count, 1) == BN - 1) {
            __threadfence();
            const float s = __ldcg(&g_sum);
            *out = s / (512.0f + 1e-8f);
            atomicExch(&g_sum, 0.0f);   // reset for next graph replay
            atomicExch(&g_count, 0);
        }
    }
}

extern "C" void kernel_launch(void* const* d_in, const int* in_sizes, int n_in,
                              void* d_out, int out_size)
{
    const float* pred = (const float*)d_in[0];
    const float* tgt  = (const float*)d_in[1];
    const float* vis  = (const float*)d_in[2];
    const float* grid = (const float*)d_in[3];
    gkl_fused_kernel<<<BN, NTHR>>>(pred, tgt, vis, grid, (float*)d_out);
}

// round 13
// speedup vs baseline: 1.1590x; 1.0983x over previous
#include <cuda_runtime.h>
#include <cuda_bf16.h>

// GaussianKernelLoss: B=32, N=16, H=W=256, SIGMA=0.1, RADIUS=0.2
// d_in[0]=pred [32,16,2] f32, d_in[1]=target [32,16,2] f32,
// d_in[2]=visibility [32,16] f32, d_in[3]=coord_grid [2,256,256] f32 (linspace i/255)
// Output: scalar f32.

#define BN     512
#define RADIUS 0.2f
#define R2     (0.2f * 0.2f)
#define COEF   (-50.0f)        // -1/(2*sigma^2)
#define INV255 (1.0f / 255.0f)
#define NCOL   4               // 4*32 = 128 >= max bbox width (<=104 exact)
#define NTHR   256             // 8 warps per block, 1 landmark per block

__device__ float gQ[BN];       // per-landmark quotients (spread stores, no chain)
__device__ int   g_count;      // zero-init; last block resets each launch

__global__ __launch_bounds__(NTHR)
void gkl_fused_kernel(const float* __restrict__ pred,
                      const float* __restrict__ tgt,
                      const float* __restrict__ vis,
                      const float* __restrict__ grid,
                      float* __restrict__ out)
{
    const int lm  = blockIdx.x;
    const int tid = threadIdx.x;
    const int cx  = tid & 31;   // lane -> column subset
    const int cy  = tid >> 5;   // warp (0..7) -> row residue (stride 8)

    __shared__ float redN[8], redD[8];
    __shared__ int   sIsLast;

    // Issue all three input loads back-to-back so their latencies overlap.
    const float  v   = vis[lm];
    const float2 t2v = ((const float2*)tgt)[lm];
    const float2 p2v = ((const float2*)pred)[lm];

    float num0 = 0.0f, den0 = 0.0f;     // two independent accumulator chains
    float num1 = 0.0f, den1 = 0.0f;

    if (v >= 0.5f) {
        const float tx = t2v.x, ty = t2v.y;
        const float px = p2v.x, py = p2v.y;

        // Exact bounding box of the radius disk (per-pixel mask is exact).
        const int x0 = max(0,   (int)floorf((tx - RADIUS) * 255.0f));
        const int y0 = max(0,   (int)floorf((ty - RADIUS) * 255.0f));
        const int x1 = min(255, (int)ceilf ((tx + RADIUS) * 255.0f));
        const int y1 = min(255, (int)ceilf ((ty + RADIUS) * 255.0f));
        const int bw = x1 - x0 + 1;
        const int bh = y1 - y0 + 1;

        // Column tables in registers: lane cx owns columns cx + 32k.
        // Out-of-range columns poisoned (Ex=0, T2=huge) -> contribute 0.
        float cT2[NCOL], cP2[NCOL], cEx[NCOL];
        #pragma unroll
        for (int k = 0; k < NCOL; k++) {
            const int j   = cx + 32 * k;
            const bool ok = (j < bw);
            const float xv = (float)(x0 + j) * INV255;   // coord_grid == linspace
            const float dt = xv - tx;
            const float dp = xv - px;
            cT2[k] = ok ? dt * dt : 1e9f;
            cP2[k] = dp * dp;
            cEx[k] = ok ? __expf(COEF * dt * dt) : 0.0f;
        }

        // Incremental row coordinates: chain A = rows cy+16n, chain B = rows
        // cy+8+16n; both advanced by 16*INV255 per iteration (stride-8 overall).
        const float base = (float)y0 * INV255;
        float dtyA = fmaf((float)cy,       INV255, base - ty);
        float dpyA = fmaf((float)cy,       INV255, base - py);
        float dtyB = fmaf((float)(cy + 8), INV255, base - ty);
        float dpyB = fmaf((float)(cy + 8), INV255, base - py);
        const float STEP = 16.0f * INV255;

        int i = cy;
        for (; i + 8 < bh; i += 16) {
            {   // row i (chain A)
                const float t2y = dtyA * dtyA;
                const float p2y = dpyA * dpyA;
                const float ey  = __expf(COEF * t2y);
                const float lim = R2 - t2y;
                #pragma unroll
                for (int k = 0; k < NCOL; k++) {
                    const float d2p = cP2[k] + p2y;
                    const float w   = cEx[k] * ey;
                    float d;
                    asm("sqrt.approx.f32 %0, %1;" : "=f"(d) : "f"(d2p));
                    if (cT2[k] <= lim) {
                        num0 = fmaf(w, d, num0);
                        den0 += w;
                    }
                }
                dtyA += STEP; dpyA += STEP;
            }
            {   // row i+8 (chain B)
                const float t2y = dtyB * dtyB;
                const float p2y = dpyB * dpyB;
                const float ey  = __expf(COEF * t2y);
                const float lim = R2 - t2y;
                #pragma unroll
                for (int k = 0; k < NCOL; k++) {
                    const float d2p = cP2[k] + p2y;
                    const float w   = cEx[k] * ey;
                    float d;
                    asm("sqrt.approx.f32 %0, %1;" : "=f"(d) : "f"(d2p));
                    if (cT2[k] <= lim) {
                        num1 = fmaf(w, d, num1);
                        den1 += w;
                    }
                }
                dtyB += STEP; dpyB += STEP;
            }
        }
        if (i < bh) {   // remainder row (chain A)
            const float t2y = dtyA * dtyA;
            const float p2y = dpyA * dpyA;
            const float ey  = __expf(COEF * t2y);
            const float lim = R2 - t2y;
            #pragma unroll
            for (int k = 0; k < NCOL; k++) {
                const float d2p = cP2[k] + p2y;
                const float w   = cEx[k] * ey;
                float d;
                asm("sqrt.approx.f32 %0, %1;" : "=f"(d) : "f"(d2p));
                if (cT2[k] <= lim) {
                    num0 = fmaf(w, d, num0);
                    den0 += w;
                }
            }
        }
    }

    float num = num0 + num1;
    float den = den0 + den1;

    // Block reduction (8 warps) — uniform path for all blocks.
    #pragma unroll
    for (int o = 16; o; o >>= 1) {
        num += __shfl_xor_sync(0xffffffffu, num, o);
        den += __shfl_xor_sync(0xffffffffu, den, o);
    }
    if (cx == 0) { redN[cy] = num; redD[cy] = den; }
    __syncthreads();

    if (tid == 0) {
        float n = 0.0f, d = 0.0f;
        #pragma unroll
        for (int k = 0; k < 8; k++) { n += redN[k]; d += redD[k]; }
        gQ[lm] = n / (d + 1e-8f);      // invisible: 0/1e-8 = 0 (off the tail path)
        __threadfence();
        const int c = atomicAdd(&g_count, 1);
        sIsLast = (c == BN - 1);
    }
    __syncthreads();

    // Last block folds the 512 quotients into the scalar output.
    if (sIsLast) {
        __threadfence();                        // acquire side of the arrival
        float s = __ldcg(&gQ[tid]) + __ldcg(&gQ[tid + 256]);
        #pragma unroll
        for (int o = 16; o; o >>= 1) s += __shfl_xor_sync(0xffffffffu, s, o);
        if (cx == 0) redN[cy] = s;
        __syncthreads();
        if (tid == 0) {
            float t = 0.0f;
            #pragma unroll
            for (int k = 0; k < 8; k++) t += redN[k];
            *out = t / (512.0f + 1e-8f);
            g_count = 0;                        // reset for next graph replay
        }
    }
}

extern "C" void kernel_launch(void* const* d_in, const int* in_sizes, int n_in,
                              void* d_out, int out_size)
{
    const float* pred = (const float*)d_in[0];
    const float* tgt  = (const float*)d_in[1];
    const float* vis  = (const float*)d_in[2];
    const float* grid = (const float*)d_in[3];
    gkl_fused_kernel<<<BN, NTHR>>>(pred, tgt, vis, grid, (float*)d_out);
}